// round 2
// baseline (speedup 1.0000x reference)
#include <cuda_runtime.h>
#include <math.h>

#define K_DIM   256
#define N1      64
#define TM      128
#define KC      64
#define NCHUNK  (K_DIM / KC)   // 4
#define THREADS 256
#define XPAD    68             // KC + 4, keeps float4 alignment, breaks bank stride

// shared memory layout (floats)
#define W1S_F   (K_DIM * N1)        // 16384 : W1s[k*64 + n]
#define XS_F    (2 * TM * XPAD)     // 17408 : double-buffered x tile [row][k]
#define W2S_F   (4 * 64)            // 256
#define SMEM_FLOATS (W1S_F + XS_F + W2S_F + 4 + 16 + 16)
#define SMEM_BYTES  (SMEM_FLOATS * 4)   // 136336

__device__ __forceinline__ void cp_async16(float* sdst, const float* gsrc) {
    unsigned saddr = (unsigned)__cvta_generic_to_shared(sdst);
    asm volatile("cp.async.cg.shared.global [%0], [%1], 16;\n"
                 :: "r"(saddr), "l"(gsrc) : "memory");
}
__device__ __forceinline__ void cp_commit() {
    asm volatile("cp.async.commit_group;\n" ::: "memory");
}
template <int N>
__device__ __forceinline__ void cp_wait() {
    asm volatile("cp.async.wait_group %0;\n" :: "n"(N) : "memory");
}

extern "C" __global__ void __launch_bounds__(THREADS, 1)
qc_fused_kernel(const float* __restrict__ x,  const float* __restrict__ W1,
                const float* __restrict__ b1, const float* __restrict__ W2,
                const float* __restrict__ b2, const float* __restrict__ qw,
                float* __restrict__ out)
{
    extern __shared__ float smem[];
    float* W1s = smem;              // [256][64] k-major
    float* Xs  = W1s + W1S_F;       // 2 x [128][XPAD]
    float* W2s = Xs + XS_F;         // [4][64]
    float* b2s = W2s + W2S_F;       // [4]
    float* cw  = b2s + 4;           // [16] cos(theta/2) of weight gates
    float* sw  = cw + 16;           // [16] sin(theta/2)

    const int t  = threadIdx.x;
    const int tx = t & 15;          // col group: cols tx*4 .. tx*4+3
    const int ty = t >> 4;          // row group: rows ty*8 .. ty*8+7
    const long row0 = (long)blockIdx.x * TM;

    // ---------- prefetch chunk 0 of x into buffer 0 ----------
    {
        #pragma unroll
        for (int i = 0; i < 8; ++i) {
            int idx = t + i * THREADS;        // [0, 2048)
            int r   = idx >> 4;               // row in tile
            int k4  = idx & 15;               // float4 slot within chunk
            cp_async16(Xs + r * XPAD + k4 * 4,
                       x + (row0 + r) * K_DIM + k4 * 4);
        }
        cp_commit();
    }

    // ---------- prologue: W1 -> SMEM transposed (k-major), small tables ----------
    #pragma unroll
    for (int i = 0; i < 16; ++i) {
        int idx = t + i * THREADS;            // [0, 4096) float4 slots
        int n   = idx & 63;
        int k4  = idx >> 6;                   // [0, 64)
        float4 v = *(const float4*)(W1 + n * K_DIM + k4 * 4);
        W1s[(k4 * 4 + 0) * 64 + n] = v.x;     // conflict-free stores (n varies in warp)
        W1s[(k4 * 4 + 1) * 64 + n] = v.y;
        W1s[(k4 * 4 + 2) * 64 + n] = v.z;
        W1s[(k4 * 4 + 3) * 64 + n] = v.w;
    }
    W2s[t] = W2[t];
    if (t < 4)  b2s[t] = b2[t];
    if (t < 16) sincosf(0.5f * qw[t], &sw[t], &cw[t]);

    float acc[8][4];
    #pragma unroll
    for (int j = 0; j < 8; ++j)
        #pragma unroll
        for (int c = 0; c < 4; ++c) acc[j][c] = 0.0f;

    // ---------- main loop: double-buffered K chunks ----------
    for (int ch = 0; ch < NCHUNK; ++ch) {
        if (ch + 1 < NCHUNK) {
            const int buf = (ch + 1) & 1;
            #pragma unroll
            for (int i = 0; i < 8; ++i) {
                int idx = t + i * THREADS;
                int r   = idx >> 4;
                int k4  = idx & 15;
                cp_async16(Xs + buf * (TM * XPAD) + r * XPAD + k4 * 4,
                           x + (row0 + r) * K_DIM + (ch + 1) * KC + k4 * 4);
            }
            cp_commit();
            cp_wait<1>();
        } else {
            cp_wait<0>();
        }
        __syncthreads();

        const float* Xb  = Xs + (ch & 1) * (TM * XPAD) + (ty * 8) * XPAD;
        const float* W1c = W1s + ch * KC * 64;   // <-- FIX: chunk offset into W1 tile

        for (int k = 0; k < KC; k += 4) {
            float4 xv[8];
            #pragma unroll
            for (int j = 0; j < 8; ++j)
                xv[j] = *(const float4*)(Xb + j * XPAD + k);
            #pragma unroll
            for (int kk = 0; kk < 4; ++kk) {
                float4 wv = *(const float4*)(W1c + (k + kk) * 64 + tx * 4);
                #pragma unroll
                for (int j = 0; j < 8; ++j) {
                    float xs = (kk == 0) ? xv[j].x :
                               (kk == 1) ? xv[j].y :
                               (kk == 2) ? xv[j].z : xv[j].w;
                    acc[j][0] += xs * wv.x;
                    acc[j][1] += xs * wv.y;
                    acc[j][2] += xs * wv.z;
                    acc[j][3] += xs * wv.w;
                }
            }
        }
        __syncthreads();
    }

    // ---------- epilogue 1: bias + relu, stage h tile in SMEM ----------
    float* Hs = Xs;   // reuse buffer 0 region: [128][XPAD]
    {
        float4 b1v = *(const float4*)(b1 + tx * 4);
        #pragma unroll
        for (int j = 0; j < 8; ++j) {
            float4 hv;
            hv.x = fmaxf(acc[j][0] + b1v.x, 0.0f);
            hv.y = fmaxf(acc[j][1] + b1v.y, 0.0f);
            hv.z = fmaxf(acc[j][2] + b1v.z, 0.0f);
            hv.w = fmaxf(acc[j][3] + b1v.w, 0.0f);
            *(float4*)(Hs + (ty * 8 + j) * XPAD + tx * 4) = hv;
        }
    }
    __syncthreads();

    // ---------- epilogue 2: per-row GEMM2 + tanh + 4-qubit circuit ----------
    if (t < TM) {
        float h[64];
        #pragma unroll
        for (int q = 0; q < 16; ++q)
            *(float4*)(h + q * 4) = *(const float4*)(Hs + t * XPAD + q * 4);

        float ang[4];
        #pragma unroll
        for (int j = 0; j < 4; ++j) {
            float s = b2s[j];
            #pragma unroll
            for (int q = 0; q < 64; ++q) s += W2s[j * 64 + q] * h[q];
            ang[j] = tanhf(s);
        }

        // statevector: idx = w0*8 + w1*4 + w2*2 + w3 (wire 0 = MSB)
        float sr[16], si[16];
        #pragma unroll
        for (int i = 0; i < 16; ++i) { sr[i] = 0.0f; si[i] = 0.0f; }
        sr[0] = 1.0f;

        // initial RY(angles[w]) on each wire
        #pragma unroll
        for (int w = 0; w < 4; ++w) {
            float c, s;
            __sincosf(0.5f * ang[w], &s, &c);
            const int m = 8 >> w;
            #pragma unroll
            for (int i0 = 0; i0 < 16; ++i0) if (!(i0 & m)) {
                const int i1 = i0 | m;
                float r0 = sr[i0], r1 = sr[i1];
                sr[i0] = c * r0 - s * r1;  sr[i1] = s * r0 + c * r1;
                float q0 = si[i0], q1 = si[i1];
                si[i0] = c * q0 - s * q1;  si[i1] = s * q0 + c * q1;
            }
        }

        #pragma unroll
        for (int l = 0; l < 2; ++l) {
            #pragma unroll
            for (int i = 0; i < 4; ++i) {
                // RY(weights[l,i,0])
                {
                    const float c = cw[l * 8 + i * 2], s = sw[l * 8 + i * 2];
                    const int m = 8 >> i;
                    #pragma unroll
                    for (int i0 = 0; i0 < 16; ++i0) if (!(i0 & m)) {
                        const int i1 = i0 | m;
                        float r0 = sr[i0], r1 = sr[i1];
                        sr[i0] = c * r0 - s * r1;  sr[i1] = s * r0 + c * r1;
                        float q0 = si[i0], q1 = si[i1];
                        si[i0] = c * q0 - s * q1;  si[i1] = s * q0 + c * q1;
                    }
                }
                // RZ(weights[l,i,1]): bit==0 -> e^{-i t/2}, bit==1 -> e^{+i t/2}
                {
                    const float c = cw[l * 8 + i * 2 + 1], s = sw[l * 8 + i * 2 + 1];
                    const int m = 8 >> i;
                    #pragma unroll
                    for (int idx = 0; idx < 16; ++idx) {
                        float re = sr[idx], im = si[idx];
                        if (idx & m) { sr[idx] = re * c - im * s;  si[idx] = im * c + re * s; }
                        else         { sr[idx] = re * c + im * s;  si[idx] = im * c - re * s; }
                    }
                }
            }
            // CNOT ring: (0,1),(1,2),(2,3),(3,0)
            #pragma unroll
            for (int cix = 0; cix < 4; ++cix) {
                const int ctrl = cix, tgt = (cix + 1) & 3;
                const int mc = 8 >> ctrl, mt = 8 >> tgt;
                #pragma unroll
                for (int idx = 0; idx < 16; ++idx)
                    if ((idx & mc) && !(idx & mt)) {
                        const int j2 = idx | mt;
                        float tr = sr[idx]; sr[idx] = sr[j2]; sr[j2] = tr;
                        float ti = si[idx]; si[idx] = si[j2]; si[j2] = ti;
                    }
            }
        }

        // <Z_0> = sum_{idx<8} |a|^2 - sum_{idx>=8} |a|^2
        float z = 0.0f;
        #pragma unroll
        for (int idx = 0; idx < 16; ++idx) {
            float p = sr[idx] * sr[idx] + si[idx] * si[idx];
            z += (idx & 8) ? -p : p;
        }
        out[row0 + t] = z;
    }
}

extern "C" void kernel_launch(void* const* d_in, const int* in_sizes, int n_in,
                              void* d_out, int out_size) {
    const float* x  = (const float*)d_in[0];
    const float* W1 = (const float*)d_in[1];
    const float* b1 = (const float*)d_in[2];
    const float* W2 = (const float*)d_in[3];
    const float* b2 = (const float*)d_in[4];
    const float* qw = (const float*)d_in[5];
    float* out = (float*)d_out;

    const int B = in_sizes[0] / K_DIM;   // 65536
    cudaFuncSetAttribute(qc_fused_kernel,
                         cudaFuncAttributeMaxDynamicSharedMemorySize, SMEM_BYTES);
    qc_fused_kernel<<<B / TM, THREADS, SMEM_BYTES>>>(x, W1, b1, W2, b2, qw, out);
}

// round 5
// speedup vs baseline: 1.9784x; 1.9784x over previous
#include <cuda_runtime.h>
#include <cuda_bf16.h>
#include <math.h>
#include <stdint.h>

#define THREADS 256
#define TM      128
#define KD      256
#define NN      64
#define KC      64          // K chunk
#define NCH     4

#define AS      72          // bf16 per A-chunk row (64 + 8 pad)
#define BS      264         // bf16 per B row (256 + 8 pad)
#define HSP     68          // floats per Hs row
#define ACHUNK  (TM * AS * 2)        // 18432 B

// byte offsets in dynamic smem
#define OFF_B1  0            // 64 f
#define OFF_B2  256          // 4 f
#define OFF_CW  272          // 16 f
#define OFF_SW  336          // 16 f
#define OFF_W2  400          // 256 f -> ends 1424
#define OFF_AH  1536                         // 2 bufs
#define OFF_AL  (OFF_AH + 2 * ACHUNK)        // 38400
#define OFF_BH  (OFF_AL + 2 * ACHUNK)        // 75264
#define OFF_BL  (OFF_BH + NN * BS * 2)       // 109056
#define SMEM_BYTES (OFF_BL + NN * BS * 2)    // 142848
#define OFF_HS  OFF_AH                       // 128*68*4 = 34816 <= 36864

__device__ __forceinline__ void ldm_x4(uint32_t& r0, uint32_t& r1, uint32_t& r2, uint32_t& r3,
                                       uint32_t addr) {
    asm volatile("ldmatrix.sync.aligned.m8n8.x4.shared.b16 {%0,%1,%2,%3}, [%4];"
                 : "=r"(r0), "=r"(r1), "=r"(r2), "=r"(r3) : "r"(addr));
}
__device__ __forceinline__ void mma_bf16(float* c, uint32_t a0, uint32_t a1, uint32_t a2,
                                         uint32_t a3, uint32_t b0, uint32_t b1) {
    asm volatile("mma.sync.aligned.m16n8k16.row.col.f32.bf16.bf16.f32 "
                 "{%0,%1,%2,%3}, {%4,%5,%6,%7}, {%8,%9}, {%0,%1,%2,%3};"
                 : "+f"(c[0]), "+f"(c[1]), "+f"(c[2]), "+f"(c[3])
                 : "r"(a0), "r"(a1), "r"(a2), "r"(a3), "r"(b0), "r"(b1));
}

extern "C" __global__ void __launch_bounds__(THREADS, 1)
qc_hmma_kernel(const float* __restrict__ x,  const float* __restrict__ W1,
               const float* __restrict__ b1, const float* __restrict__ W2,
               const float* __restrict__ b2, const float* __restrict__ qw,
               float* __restrict__ out)
{
    extern __shared__ char sm[];
    const uint32_t sb = (uint32_t)__cvta_generic_to_shared(sm);
    const int t   = threadIdx.x;
    const int wid = t >> 5;
    const int lid = t & 31;
    const int wr  = wid >> 1;       // warp row (0..3) -> rows wr*32..+31
    const int wc  = wid & 1;        // warp col (0..1) -> cols wc*32..+31
    const long row0 = (long)blockIdx.x * TM;

    float* b1s = (float*)(sm + OFF_B1);
    float* b2s = (float*)(sm + OFF_B2);
    float* cw  = (float*)(sm + OFF_CW);
    float* sw  = (float*)(sm + OFF_SW);
    float* W2s = (float*)(sm + OFF_W2);

    // ---- small tables ----
    if (t < 64)  b1s[t] = b1[t];
    if (t < 4)   b2s[t] = b2[t];
    if (t < 16)  sincosf(0.5f * qw[t], &sw[t], &cw[t]);
    W2s[t] = W2[t];

    // ---- W1 -> smem bf16 hi/lo, padded rows (8 bytes per 4-bf16 slot) ----
    #pragma unroll
    for (int i = 0; i < 16; ++i) {
        int idx = t + i * THREADS;          // [0,4096) float4 slots
        int row = idx >> 6;                 // n (0..63)
        int k4  = idx & 63;
        float4 v = *(const float4*)(W1 + row * KD + k4 * 4);
        __nv_bfloat162 h0 = __floats2bfloat162_rn(v.x, v.y);
        __nv_bfloat162 h1 = __floats2bfloat162_rn(v.z, v.w);
        __nv_bfloat162 l0 = __floats2bfloat162_rn(v.x - __bfloat162float(h0.x),
                                                  v.y - __bfloat162float(h0.y));
        __nv_bfloat162 l1 = __floats2bfloat162_rn(v.z - __bfloat162float(h1.x),
                                                  v.w - __bfloat162float(h1.y));
        uint32_t o = (uint32_t)row * (BS * 2) + (uint32_t)k4 * 8;   // FIX: 8 B/slot
        *(__nv_bfloat162*)(sm + OFF_BH + o)     = h0;
        *(__nv_bfloat162*)(sm + OFF_BH + o + 4) = h1;
        *(__nv_bfloat162*)(sm + OFF_BL + o)     = l0;
        *(__nv_bfloat162*)(sm + OFF_BL + o + 4) = l1;
    }

    // ---- x chunk loader helpers ----
    float4 xv[8];
    const float* xg = x + row0 * KD;
    auto load_chunk = [&](int ch) {
        #pragma unroll
        for (int i = 0; i < 8; ++i) {
            int idx = t + i * THREADS;      // [0,2048)
            int r   = idx >> 4;
            int s4  = idx & 15;
            xv[i] = *(const float4*)(xg + r * KD + ch * KC + s4 * 4);
        }
    };
    auto store_chunk = [&](int buf) {
        #pragma unroll
        for (int i = 0; i < 8; ++i) {
            int idx = t + i * THREADS;
            int r   = idx >> 4;
            int s4  = idx & 15;
            float4 v = xv[i];
            __nv_bfloat162 h0 = __floats2bfloat162_rn(v.x, v.y);
            __nv_bfloat162 h1 = __floats2bfloat162_rn(v.z, v.w);
            __nv_bfloat162 l0 = __floats2bfloat162_rn(v.x - __bfloat162float(h0.x),
                                                      v.y - __bfloat162float(h0.y));
            __nv_bfloat162 l1 = __floats2bfloat162_rn(v.z - __bfloat162float(h1.x),
                                                      v.w - __bfloat162float(h1.y));
            uint32_t o = (uint32_t)buf * ACHUNK + (uint32_t)r * (AS * 2)
                       + (uint32_t)s4 * 8;                           // FIX: 8 B/slot
            *(__nv_bfloat162*)(sm + OFF_AH + o)     = h0;
            *(__nv_bfloat162*)(sm + OFF_AH + o + 4) = h1;
            *(__nv_bfloat162*)(sm + OFF_AL + o)     = l0;
            *(__nv_bfloat162*)(sm + OFF_AL + o + 4) = l1;
        }
    };

    load_chunk(0);
    store_chunk(0);
    __syncthreads();

    // ---- accumulators: [mi][ni][4] ----
    float acc[2][4][4];
    #pragma unroll
    for (int mi = 0; mi < 2; ++mi)
        #pragma unroll
        for (int ni = 0; ni < 4; ++ni)
            #pragma unroll
            for (int c = 0; c < 4; ++c) acc[mi][ni][c] = 0.0f;

    // per-thread ldmatrix base addresses
    const uint32_t aRowOff = (uint32_t)(wr * 32 + (lid & 15)) * (AS * 2) + (uint32_t)(lid >> 4) * 16;
    const uint32_t bRow    = (uint32_t)(wc * 32 + ((lid >> 4) << 3) + (lid & 7));
    const uint32_t bKhalf  = (uint32_t)((lid >> 3) & 1) * 16;   // bytes
    const uint32_t bOffBase = bRow * (BS * 2) + bKhalf;

    for (int ch = 0; ch < NCH; ++ch) {
        if (ch + 1 < NCH) load_chunk(ch + 1);

        const int buf = ch & 1;
        const uint32_t aH = sb + OFF_AH + buf * ACHUNK + aRowOff;
        const uint32_t aL = sb + OFF_AL + buf * ACHUNK + aRowOff;
        const uint32_t bH = sb + OFF_BH + bOffBase + (uint32_t)ch * KC * 2;
        const uint32_t bL = sb + OFF_BL + bOffBase + (uint32_t)ch * KC * 2;

        #pragma unroll
        for (int ks = 0; ks < 4; ++ks) {
            #pragma unroll
            for (int pass = 0; pass < 3; ++pass) {
                const uint32_t aAddr = ((pass == 2) ? aL : aH) + ks * 32;
                const uint32_t bAddr = ((pass == 1) ? bL : bH) + ks * 32;
                uint32_t a0[4], a1[4], b0[4], b1f[4];
                ldm_x4(a0[0], a0[1], a0[2], a0[3], aAddr);                     // rows wr*32..+15
                ldm_x4(a1[0], a1[1], a1[2], a1[3], aAddr + 16 * (AS * 2));     // rows +16
                ldm_x4(b0[0], b0[1], b0[2], b0[3], bAddr);                     // n-tiles 0,1
                ldm_x4(b1f[0], b1f[1], b1f[2], b1f[3], bAddr + 16 * (BS * 2)); // n-tiles 2,3
                #pragma unroll
                for (int ni = 0; ni < 4; ++ni) {
                    uint32_t rb0 = (ni < 2) ? b0[(ni & 1) * 2]     : b1f[(ni & 1) * 2];
                    uint32_t rb1 = (ni < 2) ? b0[(ni & 1) * 2 + 1] : b1f[(ni & 1) * 2 + 1];
                    mma_bf16(acc[0][ni], a0[0], a0[1], a0[2], a0[3], rb0, rb1);
                    mma_bf16(acc[1][ni], a1[0], a1[1], a1[2], a1[3], rb0, rb1);
                }
            }
        }

        if (ch + 1 < NCH) store_chunk(buf ^ 1);
        __syncthreads();
    }

    // ---- stage H tile (fp32) in smem ----
    float* Hs = (float*)(sm + OFF_HS);
    {
        #pragma unroll
        for (int mi = 0; mi < 2; ++mi)
            #pragma unroll
            for (int ni = 0; ni < 4; ++ni) {
                int row = wr * 32 + mi * 16 + (lid >> 2);
                int col = wc * 32 + ni * 8 + (lid & 3) * 2;
                *(float2*)&Hs[row * HSP + col]       = make_float2(acc[mi][ni][0], acc[mi][ni][1]);
                *(float2*)&Hs[(row + 8) * HSP + col] = make_float2(acc[mi][ni][2], acc[mi][ni][3]);
            }
    }
    __syncthreads();

    // ---- per-row epilogue: bias+relu, GEMM2+tanh, 4-qubit circuit ----
    if (t < TM) {
        float h[64];
        #pragma unroll
        for (int q = 0; q < 16; ++q)
            *(float4*)(h + q * 4) = *(const float4*)(Hs + t * HSP + q * 4);
        #pragma unroll
        for (int q = 0; q < 64; ++q) h[q] = fmaxf(h[q] + b1s[q], 0.0f);

        float ang[4];
        #pragma unroll
        for (int j = 0; j < 4; ++j) {
            float s = b2s[j];
            #pragma unroll
            for (int q = 0; q < 64; ++q) s += W2s[j * 64 + q] * h[q];
            ang[j] = tanhf(s);
        }

        float sr[16], si[16];
        #pragma unroll
        for (int i = 0; i < 16; ++i) { sr[i] = 0.0f; si[i] = 0.0f; }
        sr[0] = 1.0f;

        #pragma unroll
        for (int w = 0; w < 4; ++w) {
            float c, s;
            __sincosf(0.5f * ang[w], &s, &c);
            const int m = 8 >> w;
            #pragma unroll
            for (int i0 = 0; i0 < 16; ++i0) if (!(i0 & m)) {
                const int i1 = i0 | m;
                float r0 = sr[i0], r1 = sr[i1];
                sr[i0] = c * r0 - s * r1;  sr[i1] = s * r0 + c * r1;
                float q0 = si[i0], q1 = si[i1];
                si[i0] = c * q0 - s * q1;  si[i1] = s * q0 + c * q1;
            }
        }

        #pragma unroll
        for (int l = 0; l < 2; ++l) {
            #pragma unroll
            for (int i = 0; i < 4; ++i) {
                {   // RY(weights[l,i,0])
                    const float c = cw[l * 8 + i * 2], s = sw[l * 8 + i * 2];
                    const int m = 8 >> i;
                    #pragma unroll
                    for (int i0 = 0; i0 < 16; ++i0) if (!(i0 & m)) {
                        const int i1 = i0 | m;
                        float r0 = sr[i0], r1 = sr[i1];
                        sr[i0] = c * r0 - s * r1;  sr[i1] = s * r0 + c * r1;
                        float q0 = si[i0], q1 = si[i1];
                        si[i0] = c * q0 - s * q1;  si[i1] = s * q0 + c * q1;
                    }
                }
                {   // RZ(weights[l,i,1])
                    const float c = cw[l * 8 + i * 2 + 1], s = sw[l * 8 + i * 2 + 1];
                    const int m = 8 >> i;
                    #pragma unroll
                    for (int idx = 0; idx < 16; ++idx) {
                        float re = sr[idx], im = si[idx];
                        if (idx & m) { sr[idx] = re * c - im * s;  si[idx] = im * c + re * s; }
                        else         { sr[idx] = re * c + im * s;  si[idx] = im * c - re * s; }
                    }
                }
            }
            #pragma unroll
            for (int cix = 0; cix < 4; ++cix) {
                const int ctrl = cix, tgt = (cix + 1) & 3;
                const int mc = 8 >> ctrl, mt = 8 >> tgt;
                #pragma unroll
                for (int idx = 0; idx < 16; ++idx)
                    if ((idx & mc) && !(idx & mt)) {
                        const int j2 = idx | mt;
                        float tr = sr[idx]; sr[idx] = sr[j2]; sr[j2] = tr;
                        float ti = si[idx]; si[idx] = si[j2]; si[j2] = ti;
                    }
            }
        }

        float z = 0.0f;
        #pragma unroll
        for (int idx = 0; idx < 16; ++idx) {
            float p = sr[idx] * sr[idx] + si[idx] * si[idx];
            z += (idx & 8) ? -p : p;
        }
        out[row0 + t] = z;
    }
}

extern "C" void kernel_launch(void* const* d_in, const int* in_sizes, int n_in,
                              void* d_out, int out_size) {
    const float* x  = (const float*)d_in[0];
    const float* W1 = (const float*)d_in[1];
    const float* b1 = (const float*)d_in[2];
    const float* W2 = (const float*)d_in[3];
    const float* b2 = (const float*)d_in[4];
    const float* qw = (const float*)d_in[5];
    float* out = (float*)d_out;

    const int B = in_sizes[0] / KD;   // 65536
    cudaFuncSetAttribute(qc_hmma_kernel,
                         cudaFuncAttributeMaxDynamicSharedMemorySize, SMEM_BYTES);
    qc_hmma_kernel<<<B / TM, THREADS, SMEM_BYTES>>>(x, W1, b1, W2, b2, qw, out);
}

// round 6
// speedup vs baseline: 2.4635x; 1.2452x over previous
#include <cuda_runtime.h>
#include <cuda_bf16.h>
#include <math.h>
#include <stdint.h>

#define THREADS 256
#define TM      128
#define KD      256
#define NN      64
#define KC      64
#define NCH     4

#define AS      72           // bf16 per A row (64 + 8 pad)  -> 144 B
#define BS      264          // bf16 per B row (256 + 8 pad) -> 528 B
#define HSP     68
#define A_PLANE (TM * AS * 2)        // 18432 B

// smem byte offsets
#define OFF_B1  0            // 64 f
#define OFF_B2  256          // 4 f
#define OFF_CW  272          // 16 f
#define OFF_SW  336          // 16 f
#define OFF_W2T 400          // 256 f (transposed [q][j]) -> ends 1424
#define OFF_AH  1536
#define OFF_AL  (OFF_AH + A_PLANE)       // 19968
#define OFF_BH  (OFF_AL + A_PLANE)       // 38400
#define OFF_BL  (OFF_BH + NN * BS * 2)   // 72192
#define SMEM_BYTES (OFF_BL + NN * BS * 2) // 105984
#define OFF_HS  OFF_AH       // 128*68*4 = 34816 <= 36864 (A region)

__device__ __forceinline__ void ldm_x4(uint32_t& r0, uint32_t& r1, uint32_t& r2, uint32_t& r3,
                                       uint32_t addr) {
    asm volatile("ldmatrix.sync.aligned.m8n8.x4.shared.b16 {%0,%1,%2,%3}, [%4];"
                 : "=r"(r0), "=r"(r1), "=r"(r2), "=r"(r3) : "r"(addr));
}
__device__ __forceinline__ void mma_bf16(float* c, const uint32_t* a, uint32_t b0, uint32_t b1) {
    asm volatile("mma.sync.aligned.m16n8k16.row.col.f32.bf16.bf16.f32 "
                 "{%0,%1,%2,%3}, {%4,%5,%6,%7}, {%8,%9}, {%0,%1,%2,%3};"
                 : "+f"(c[0]), "+f"(c[1]), "+f"(c[2]), "+f"(c[3])
                 : "r"(a[0]), "r"(a[1]), "r"(a[2]), "r"(a[3]), "r"(b0), "r"(b1));
}

extern "C" __global__ void __launch_bounds__(THREADS, 2)
qc_hmma2_kernel(const float* __restrict__ x,  const float* __restrict__ W1,
                const float* __restrict__ b1, const float* __restrict__ W2,
                const float* __restrict__ b2, const float* __restrict__ qw,
                float* __restrict__ out)
{
    extern __shared__ char sm[];
    const uint32_t sb = (uint32_t)__cvta_generic_to_shared(sm);
    const int t   = threadIdx.x;
    const int wid = t >> 5;
    const int lid = t & 31;
    const int wr  = wid >> 1;
    const int wc  = wid & 1;
    const long row0 = (long)blockIdx.x * TM;

    float* b1s = (float*)(sm + OFF_B1);
    float* b2s = (float*)(sm + OFF_B2);
    float* cw  = (float*)(sm + OFF_CW);
    float* sw  = (float*)(sm + OFF_SW);
    float* W2t = (float*)(sm + OFF_W2T);

    if (t < 64)  b1s[t] = b1[t];
    if (t < 4)   b2s[t] = b2[t];
    if (t < 16)  sincosf(0.5f * qw[t], &sw[t], &cw[t]);
    { int j = t >> 6, q = t & 63; W2t[q * 4 + j] = W2[t]; }   // transpose W2

    // ---- W1 -> smem bf16 hi/lo ----
    #pragma unroll
    for (int i = 0; i < 16; ++i) {
        int idx = t + i * THREADS;
        int row = idx >> 6;
        int k4  = idx & 63;
        float4 v = *(const float4*)(W1 + row * KD + k4 * 4);
        __nv_bfloat162 h0 = __floats2bfloat162_rn(v.x, v.y);
        __nv_bfloat162 h1 = __floats2bfloat162_rn(v.z, v.w);
        __nv_bfloat162 l0 = __floats2bfloat162_rn(v.x - __bfloat162float(h0.x),
                                                  v.y - __bfloat162float(h0.y));
        __nv_bfloat162 l1 = __floats2bfloat162_rn(v.z - __bfloat162float(h1.x),
                                                  v.w - __bfloat162float(h1.y));
        uint32_t o = (uint32_t)row * (BS * 2) + (uint32_t)k4 * 8;
        *(uint2*)(sm + OFF_BH + o) = make_uint2(*(uint32_t*)&h0, *(uint32_t*)&h1);
        *(uint2*)(sm + OFF_BL + o) = make_uint2(*(uint32_t*)&l0, *(uint32_t*)&l1);
    }

    float4 xv[8];
    const float* xg = x + row0 * KD;
    auto load_chunk = [&](int ch) {
        #pragma unroll
        for (int i = 0; i < 8; ++i) {
            int idx = t + i * THREADS;
            int r   = idx >> 4;
            int s4  = idx & 15;
            xv[i] = *(const float4*)(xg + r * KD + ch * KC + s4 * 4);
        }
    };
    auto store_chunk = [&]() {
        #pragma unroll
        for (int i = 0; i < 8; ++i) {
            int idx = t + i * THREADS;
            int r   = idx >> 4;
            int s4  = idx & 15;
            float4 v = xv[i];
            __nv_bfloat162 h0 = __floats2bfloat162_rn(v.x, v.y);
            __nv_bfloat162 h1 = __floats2bfloat162_rn(v.z, v.w);
            __nv_bfloat162 l0 = __floats2bfloat162_rn(v.x - __bfloat162float(h0.x),
                                                      v.y - __bfloat162float(h0.y));
            __nv_bfloat162 l1 = __floats2bfloat162_rn(v.z - __bfloat162float(h1.x),
                                                      v.w - __bfloat162float(h1.y));
            uint32_t o = (uint32_t)r * (AS * 2) + (uint32_t)s4 * 8;
            *(uint2*)(sm + OFF_AH + o) = make_uint2(*(uint32_t*)&h0, *(uint32_t*)&h1);
            *(uint2*)(sm + OFF_AL + o) = make_uint2(*(uint32_t*)&l0, *(uint32_t*)&l1);
        }
    };

    load_chunk(0);
    store_chunk();
    __syncthreads();

    float acc[2][4][4];
    #pragma unroll
    for (int mi = 0; mi < 2; ++mi)
        #pragma unroll
        for (int ni = 0; ni < 4; ++ni)
            #pragma unroll
            for (int c = 0; c < 4; ++c) acc[mi][ni][c] = 0.0f;

    const uint32_t aRowOff = (uint32_t)(wr * 32 + (lid & 15)) * (AS * 2) + (uint32_t)(lid >> 4) * 16;
    const uint32_t bRow    = (uint32_t)(wc * 32 + ((lid >> 4) << 3) + (lid & 7));
    const uint32_t bKhalf  = (uint32_t)((lid >> 3) & 1) * 16;
    const uint32_t bOffBase = bRow * (BS * 2) + bKhalf;

    for (int ch = 0; ch < NCH; ++ch) {
        if (ch + 1 < NCH) load_chunk(ch + 1);   // global loads overlap MMA below

        const uint32_t aHb = sb + OFF_AH + aRowOff;
        const uint32_t aLb = sb + OFF_AL + aRowOff;
        const uint32_t bHb = sb + OFF_BH + bOffBase + (uint32_t)ch * KC * 2;
        const uint32_t bLb = sb + OFF_BL + bOffBase + (uint32_t)ch * KC * 2;

        #pragma unroll
        for (int ks = 0; ks < 4; ++ks) {
            uint32_t ah0[4], ah1[4], al0[4], al1[4];
            uint32_t bh0[4], bh1[4], bl0[4], bl1[4];
            ldm_x4(ah0[0], ah0[1], ah0[2], ah0[3], aHb + ks * 32);
            ldm_x4(ah1[0], ah1[1], ah1[2], ah1[3], aHb + ks * 32 + 16 * (AS * 2));
            ldm_x4(al0[0], al0[1], al0[2], al0[3], aLb + ks * 32);
            ldm_x4(al1[0], al1[1], al1[2], al1[3], aLb + ks * 32 + 16 * (AS * 2));
            ldm_x4(bh0[0], bh0[1], bh0[2], bh0[3], bHb + ks * 32);
            ldm_x4(bh1[0], bh1[1], bh1[2], bh1[3], bHb + ks * 32 + 16 * (BS * 2));
            ldm_x4(bl0[0], bl0[1], bl0[2], bl0[3], bLb + ks * 32);
            ldm_x4(bl1[0], bl1[1], bl1[2], bl1[3], bLb + ks * 32 + 16 * (BS * 2));

            #pragma unroll
            for (int ni = 0; ni < 4; ++ni) {
                uint32_t hb0 = (ni < 2) ? bh0[(ni & 1) * 2]     : bh1[(ni & 1) * 2];
                uint32_t hb1 = (ni < 2) ? bh0[(ni & 1) * 2 + 1] : bh1[(ni & 1) * 2 + 1];
                uint32_t lb0 = (ni < 2) ? bl0[(ni & 1) * 2]     : bl1[(ni & 1) * 2];
                uint32_t lb1 = (ni < 2) ? bl0[(ni & 1) * 2 + 1] : bl1[(ni & 1) * 2 + 1];
                mma_bf16(acc[0][ni], ah0, hb0, hb1);   // Ah*Bh
                mma_bf16(acc[1][ni], ah1, hb0, hb1);
                mma_bf16(acc[0][ni], ah0, lb0, lb1);   // Ah*Bl
                mma_bf16(acc[1][ni], ah1, lb0, lb1);
                mma_bf16(acc[0][ni], al0, hb0, hb1);   // Al*Bh
                mma_bf16(acc[1][ni], al1, hb0, hb1);
            }
        }

        __syncthreads();                        // all A reads done
        if (ch + 1 < NCH) { store_chunk(); __syncthreads(); }
    }

    // ---- stage H tile (fp32) in smem (reuses A region) ----
    float* Hs = (float*)(sm + OFF_HS);
    {
        #pragma unroll
        for (int mi = 0; mi < 2; ++mi)
            #pragma unroll
            for (int ni = 0; ni < 4; ++ni) {
                int row = wr * 32 + mi * 16 + (lid >> 2);
                int col = wc * 32 + ni * 8 + (lid & 3) * 2;
                *(float2*)&Hs[row * HSP + col]       = make_float2(acc[mi][ni][0], acc[mi][ni][1]);
                *(float2*)&Hs[(row + 8) * HSP + col] = make_float2(acc[mi][ni][2], acc[mi][ni][3]);
            }
    }
    __syncthreads();

    // ---- per-row epilogue: streamed bias+relu+GEMM2, tanh, circuit ----
    if (t < TM) {
        float ang0 = b2s[0], ang1 = b2s[1], ang2 = b2s[2], ang3 = b2s[3];
        #pragma unroll
        for (int q4 = 0; q4 < 16; ++q4) {
            float4 h4 = *(const float4*)(Hs + t * HSP + q4 * 4);
            float4 bb = *(const float4*)(b1s + q4 * 4);
            float hq;
            #pragma unroll
            for (int i = 0; i < 4; ++i) {
                float hv = (i == 0) ? h4.x : (i == 1) ? h4.y : (i == 2) ? h4.z : h4.w;
                float bv = (i == 0) ? bb.x : (i == 1) ? bb.y : (i == 2) ? bb.z : bb.w;
                hq = fmaxf(hv + bv, 0.0f);
                float4 w = *(const float4*)(W2t + (q4 * 4 + i) * 4);
                ang0 += hq * w.x;  ang1 += hq * w.y;
                ang2 += hq * w.z;  ang3 += hq * w.w;
            }
        }
        float ang[4] = { tanhf(ang0), tanhf(ang1), tanhf(ang2), tanhf(ang3) };

        float sr[16], si[16];
        #pragma unroll
        for (int i = 0; i < 16; ++i) { sr[i] = 0.0f; si[i] = 0.0f; }
        sr[0] = 1.0f;

        #pragma unroll
        for (int w = 0; w < 4; ++w) {
            float c, s;
            __sincosf(0.5f * ang[w], &s, &c);
            const int m = 8 >> w;
            #pragma unroll
            for (int i0 = 0; i0 < 16; ++i0) if (!(i0 & m)) {
                const int i1 = i0 | m;
                float r0 = sr[i0], r1 = sr[i1];
                sr[i0] = c * r0 - s * r1;  sr[i1] = s * r0 + c * r1;
                float q0 = si[i0], q1 = si[i1];
                si[i0] = c * q0 - s * q1;  si[i1] = s * q0 + c * q1;
            }
        }

        #pragma unroll
        for (int l = 0; l < 2; ++l) {
            #pragma unroll
            for (int i = 0; i < 4; ++i) {
                {   // RY(weights[l,i,0])
                    const float c = cw[l * 8 + i * 2], s = sw[l * 8 + i * 2];
                    const int m = 8 >> i;
                    #pragma unroll
                    for (int i0 = 0; i0 < 16; ++i0) if (!(i0 & m)) {
                        const int i1 = i0 | m;
                        float r0 = sr[i0], r1 = sr[i1];
                        sr[i0] = c * r0 - s * r1;  sr[i1] = s * r0 + c * r1;
                        float q0 = si[i0], q1 = si[i1];
                        si[i0] = c * q0 - s * q1;  si[i1] = s * q0 + c * q1;
                    }
                }
                {   // RZ(weights[l,i,1])
                    const float c = cw[l * 8 + i * 2 + 1], s = sw[l * 8 + i * 2 + 1];
                    const int m = 8 >> i;
                    #pragma unroll
                    for (int idx = 0; idx < 16; ++idx) {
                        float re = sr[idx], im = si[idx];
                        if (idx & m) { sr[idx] = re * c - im * s;  si[idx] = im * c + re * s; }
                        else         { sr[idx] = re * c + im * s;  si[idx] = im * c - re * s; }
                    }
                }
            }
            #pragma unroll
            for (int cix = 0; cix < 4; ++cix) {
                const int ctrl = cix, tgt = (cix + 1) & 3;
                const int mc = 8 >> ctrl, mt = 8 >> tgt;
                #pragma unroll
                for (int idx = 0; idx < 16; ++idx)
                    if ((idx & mc) && !(idx & mt)) {
                        const int j2 = idx | mt;
                        float tr = sr[idx]; sr[idx] = sr[j2]; sr[j2] = tr;
                        float ti = si[idx]; si[idx] = si[j2]; si[j2] = ti;
                    }
            }
        }

        float z = 0.0f;
        #pragma unroll
        for (int idx = 0; idx < 16; ++idx) {
            float p = sr[idx] * sr[idx] + si[idx] * si[idx];
            z += (idx & 8) ? -p : p;
        }
        out[row0 + t] = z;
    }
}

extern "C" void kernel_launch(void* const* d_in, const int* in_sizes, int n_in,
                              void* d_out, int out_size) {
    const float* x  = (const float*)d_in[0];
    const float* W1 = (const float*)d_in[1];
    const float* b1 = (const float*)d_in[2];
    const float* W2 = (const float*)d_in[3];
    const float* b2 = (const float*)d_in[4];
    const float* qw = (const float*)d_in[5];
    float* out = (float*)d_out;

    const int B = in_sizes[0] / KD;   // 65536
    cudaFuncSetAttribute(qc_hmma2_kernel,
                         cudaFuncAttributeMaxDynamicSharedMemorySize, SMEM_BYTES);
    qc_hmma2_kernel<<<B / TM, THREADS, SMEM_BYTES>>>(x, W1, b1, W2, b2, qw, out);
}